// round 1
// baseline (speedup 1.0000x reference)
#include <cuda_runtime.h>
#include <cuda_bf16.h>

// ---------------------------------------------------------------------------
// 10-qubit state-vector simulator, one warp per batch element.
// State: 1024 complex amps = 32 per lane, held entirely in registers.
// Amplitude index k (10 bits): bits[9:5] = lane, bits[4:0] = register slot r.
// Qubit w <-> bit (9-w) of k  (matches reference reshape & Z_SIGNS).
// ---------------------------------------------------------------------------

#define NQ 10
#define NL 6
#define BATCH 16384
#define EMB 64

__device__ float g_gates[NL * NQ * 8];  // per gate: u00r,u00i,u01r,u01i,u10r,u10i,u11r,u11i

// ---- prep kernel: build the 60 batch-independent Rot matrices -------------
__global__ void prep_gates_kernel(const float* __restrict__ weights) {
    int i = threadIdx.x;
    if (i < NL * NQ) {
        float phi = weights[i * 3 + 0];
        float th  = weights[i * 3 + 1];
        float om  = weights[i * 3 + 2];
        float c, s;
        sincosf(0.5f * th, &s, &c);
        float a = 0.5f * (phi + om);
        float d = 0.5f * (phi - om);
        float sa, ca, sd, cd;
        sincosf(a, &sa, &ca);
        sincosf(d, &sd, &cd);
        float* g = g_gates + i * 8;
        // u00 = e^{-ia} c ; u01 = -e^{+id} s ; u10 = e^{-id} s ; u11 = e^{+ia} c
        g[0] =  ca * c;  g[1] = -sa * c;
        g[2] = -cd * s;  g[3] = -sd * s;
        g[4] =  cd * s;  g[5] = -sd * s;
        g[6] =  ca * c;  g[7] =  sa * c;
    }
}

__device__ __forceinline__ float shx(float v, int m) {
    return __shfl_xor_sync(0xffffffffu, v, m);
}

// ---- single-qubit gate on qubit W -----------------------------------------
template <int W>
__device__ __forceinline__ void apply_gate_u(
    float* ar, float* ai, int lane,
    float u00r, float u00i, float u01r, float u01i,
    float u10r, float u10i, float u11r, float u11i)
{
    constexpr int BIT = 9 - W;
    if constexpr (BIT >= 5) {
        // lane-bit gate: partner across lanes
        constexpr int ML = 1 << (BIT - 5);
        const bool hi = (lane & ML) != 0;
        const float cmr = hi ? u11r : u00r, cmi = hi ? u11i : u00i;
        const float cpr = hi ? u10r : u01r, cpi = hi ? u10i : u01i;
#pragma unroll
        for (int r = 0; r < 32; r++) {
            float pr = shx(ar[r], ML);
            float pi = shx(ai[r], ML);
            float mr = ar[r], mi = ai[r];
            ar[r] = cmr * mr - cmi * mi + cpr * pr - cpi * pi;
            ai[r] = cmr * mi + cmi * mr + cpr * pi + cpi * pr;
        }
    } else {
        // register-bit gate: pairs within this lane
        constexpr int M = 1 << BIT;
#pragma unroll
        for (int r = 0; r < 32; r++) {
            if ((r & M) == 0) {
                const int r1 = r | M;
                float a0r = ar[r],  a0i = ai[r];
                float a1r = ar[r1], a1i = ai[r1];
                ar[r]  = u00r * a0r - u00i * a0i + u01r * a1r - u01i * a1i;
                ai[r]  = u00r * a0i + u00i * a0r + u01r * a1i + u01i * a1r;
                ar[r1] = u10r * a0r - u10i * a0i + u11r * a1r - u11i * a1i;
                ai[r1] = u10r * a0i + u10i * a0r + u11r * a1i + u11i * a1r;
            }
        }
    }
}

// ---- CNOT(C, T): new[k] = old[k ^ (bit_C(k) ? mask_T : 0)] ----------------
template <int C, int T>
__device__ __forceinline__ void cnot_g(float* ar, float* ai, int lane) {
    constexpr int BC = 9 - C, BT = 9 - T;
    if constexpr (BC < 5 && BT < 5) {
        // both register bits: unconditional register swaps
        constexpr int MC = 1 << BC, MT = 1 << BT;
#pragma unroll
        for (int r = 0; r < 32; r++) {
            if ((r & MC) && !(r & MT)) {
                const int r1 = r | MT;
                float t;
                t = ar[r]; ar[r] = ar[r1]; ar[r1] = t;
                t = ai[r]; ai[r] = ai[r1]; ai[r1] = t;
            }
        }
    } else if constexpr (BC < 5 && BT >= 5) {
        // control in registers, target across lanes: exchange where ctrl=1
        constexpr int MC = 1 << BC, ML = 1 << (BT - 5);
#pragma unroll
        for (int r = 0; r < 32; r++) {
            if (r & MC) {
                ar[r] = shx(ar[r], ML);
                ai[r] = shx(ai[r], ML);
            }
        }
    } else if constexpr (BC >= 5 && BT < 5) {
        // control on lane bit, target in registers: predicated swap
        constexpr int MCL = 1 << (BC - 5), MT = 1 << BT;
        const bool ctrl = (lane & MCL) != 0;
#pragma unroll
        for (int r = 0; r < 32; r++) {
            if (!(r & MT)) {
                const int r1 = r | MT;
                float a0 = ar[r], a1 = ar[r1];
                ar[r]  = ctrl ? a1 : a0;
                ar[r1] = ctrl ? a0 : a1;
                float b0 = ai[r], b1 = ai[r1];
                ai[r]  = ctrl ? b1 : b0;
                ai[r1] = ctrl ? b0 : b1;
            }
        }
    } else {
        // both lane bits: gather from computed source lane
        constexpr int MCL = 1 << (BC - 5), MTL = 1 << (BT - 5);
        const int src = lane ^ ((lane & MCL) ? MTL : 0);
#pragma unroll
        for (int r = 0; r < 32; r++) {
            ar[r] = __shfl_sync(0xffffffffu, ar[r], src);
            ai[r] = __shfl_sync(0xffffffffu, ai[r], src);
        }
    }
}

// ---- compile-time circuit structure ---------------------------------------
template <int L, int W>
__device__ __forceinline__ void layer_rots(float* ar, float* ai, int lane,
                                           const float* __restrict__ sg) {
    if constexpr (W < NQ) {
        const float* u = sg + (L * NQ + W) * 8;
        apply_gate_u<W>(ar, ai, lane, u[0], u[1], u[2], u[3], u[4], u[5], u[6], u[7]);
        layer_rots<L, W + 1>(ar, ai, lane, sg);
    }
}

template <int L, int W>
__device__ __forceinline__ void layer_cnots(float* ar, float* ai, int lane) {
    if constexpr (W < NQ) {
        cnot_g<W, (W + (L % (NQ - 1)) + 1) % NQ>(ar, ai, lane);
        layer_cnots<L, W + 1>(ar, ai, lane);
    }
}

template <int L>
__device__ __forceinline__ void run_layers(float* ar, float* ai, int lane,
                                           const float* __restrict__ sg) {
    if constexpr (L < NL) {
        layer_rots<L, 0>(ar, ai, lane, sg);
        layer_cnots<L, 0>(ar, ai, lane);
        run_layers<L + 1>(ar, ai, lane, sg);
    }
}

template <int W>
__device__ __forceinline__ void init_rx(float* ar, float* ai, int lane,
                                        const float* halfang) {
    if constexpr (W < NQ) {
        float s, c;
        __sincosf(halfang[W], &s, &c);
        // RX: [[c, -is], [-is, c]]
        apply_gate_u<W>(ar, ai, lane, c, 0.f, 0.f, -s, 0.f, -s, c, 0.f);
        init_rx<W + 1>(ar, ai, lane, halfang);
    }
}

// ---- main kernel: 8 warps per block, 1 element per warp -------------------
__global__ void __launch_bounds__(256)
qsim_kernel(const float* __restrict__ x, const float* __restrict__ Wm,
            const float* __restrict__ b, float* __restrict__ out) {
    __shared__ float sW[NQ * EMB];
    __shared__ float sb[16];
    __shared__ float sg[NL * NQ * 8];

    const int tid = threadIdx.x;
    for (int i = tid; i < NQ * EMB; i += 256) sW[i] = Wm[i];
    if (tid < NQ) sb[tid] = b[tid];
    for (int i = tid; i < NL * NQ * 8; i += 256) sg[i] = g_gates[i];
    __syncthreads();

    const int lane = tid & 31;
    const int e = blockIdx.x * 8 + (tid >> 5);

    // angles = x[e] @ W.T + b  (half-angles)
    const float xa = x[e * EMB + lane];
    const float xb = x[e * EMB + 32 + lane];
    float halfang[NQ];
#pragma unroll
    for (int w = 0; w < NQ; w++) {
        float p = xa * sW[w * EMB + lane] + xb * sW[w * EMB + 32 + lane];
#pragma unroll
        for (int m = 16; m >= 1; m >>= 1) p += shx(p, m);
        halfang[w] = 0.5f * (p + sb[w]);
    }

    // |0...0>
    float ar[32], ai[32];
#pragma unroll
    for (int r = 0; r < 32; r++) { ar[r] = 0.f; ai[r] = 0.f; }
    if (lane == 0) ar[0] = 1.0f;

    // embedding RX gates, then 6 entangling layers
    init_rx<0>(ar, ai, lane, halfang);
    run_layers<0>(ar, ai, lane, sg);

    // readout: <Z_q> = sum_k sign_q(k) * |amp_k|^2
    float tot = 0.f, d0 = 0.f, d1 = 0.f, d2 = 0.f, d3 = 0.f, d4 = 0.f;
#pragma unroll
    for (int r = 0; r < 32; r++) {
        float p = ar[r] * ar[r] + ai[r] * ai[r];
        tot += p;
        d0 += (r & 1)  ? -p : p;
        d1 += (r & 2)  ? -p : p;
        d2 += (r & 4)  ? -p : p;
        d3 += (r & 8)  ? -p : p;
        d4 += (r & 16) ? -p : p;
    }
    float res[NQ];
    // qubits 0..4 live on lane bits 4..0
    res[0] = (lane & 16) ? -tot : tot;
    res[1] = (lane & 8)  ? -tot : tot;
    res[2] = (lane & 4)  ? -tot : tot;
    res[3] = (lane & 2)  ? -tot : tot;
    res[4] = (lane & 1)  ? -tot : tot;
    // qubits 5..9 live on register bits 4..0
    res[5] = d4; res[6] = d3; res[7] = d2; res[8] = d1; res[9] = d0;
#pragma unroll
    for (int q = 0; q < NQ; q++) {
#pragma unroll
        for (int m = 16; m >= 1; m >>= 1) res[q] += shx(res[q], m);
    }
#pragma unroll
    for (int q = 0; q < NQ; q++) {
        if (lane == q) out[e * NQ + q] = res[q];
    }
}

extern "C" void kernel_launch(void* const* d_in, const int* in_sizes, int n_in,
                              void* d_out, int out_size) {
    const float* x       = (const float*)d_in[0];  // (16384, 64)
    const float* Wm      = (const float*)d_in[1];  // (10, 64)
    const float* b       = (const float*)d_in[2];  // (10,)
    const float* weights = (const float*)d_in[3];  // (6, 10, 3)
    float* out = (float*)d_out;                    // (16384, 10)

    prep_gates_kernel<<<1, 64>>>(weights);
    qsim_kernel<<<BATCH / 8, 256>>>(x, Wm, b, out);
}